// round 1
// baseline (speedup 1.0000x reference)
#include <cuda_runtime.h>

// Mutual-information loss over two 2^25-element fp32 arrays.
// joint_hist == hist_x + hist_y, so only two 30-bin histograms are needed.
// Hot loop: per-lane-private shared-memory histograms (no atomics, no bank
// conflicts), then per-block warp reduce -> 30 global atomics, then a tiny
// epilogue kernel computes the MI scalar in double precision.

#define BINS 30
#define NBIN_PAD 32          // 30 real bins + overflow slot (bin 30)
#define THREADS 256
#define WARPS (THREADS / 32)
#define BPA 148              // blocks per input array (1 per SM per array)

__device__ unsigned int g_hist[2 * NBIN_PAD];  // [0..31]=x, [32..63]=y

__global__ void zero_kernel() {
    int t = threadIdx.x;
    if (t < 2 * NBIN_PAD) g_hist[t] = 0u;
}

__global__ void __launch_bounds__(THREADS) hist_kernel(
    const float* __restrict__ x, const float* __restrict__ y,
    int nx, int ny)
{
    // 8 warps * 32 bins * 32 lanes * 4B = 32 KB
    __shared__ unsigned int sh[WARPS * NBIN_PAD * 32];

    for (int i = threadIdx.x; i < WARPS * NBIN_PAD * 32; i += THREADS) sh[i] = 0u;
    __syncthreads();

    const int which = (blockIdx.x >= BPA) ? 1 : 0;
    const float* __restrict__ src = which ? y : x;
    const int n = which ? ny : nx;
    const int bid = which ? (blockIdx.x - BPA) : blockIdx.x;

    const int warp = threadIdx.x >> 5;
    const int lane = threadIdx.x & 31;
    // lane-private column: address = warp*4096B + bin*128B + lane*4B
    // -> bank(lane) always == lane: conflict-free for any bin.
    unsigned int* __restrict__ h = sh + warp * (NBIN_PAD * 32) + lane;

    const float4* __restrict__ v4 = (const float4*)src;
    const int n4 = n >> 2;
    const int stride = BPA * THREADS;

#define PROC(val) {                                         \
        float t = fmaf((val), 3.75f, 15.0f);                \
        int b = min((int)t, 29);                            \
        if (!(fabsf(val) <= 4.0f)) b = 30;                  \
        h[b << 5] += 1u; }

    #pragma unroll 4
    for (int i = bid * THREADS + threadIdx.x; i < n4; i += stride) {
        float4 v = v4[i];
        PROC(v.x)
        PROC(v.y)
        PROC(v.z)
        PROC(v.w)
    }
#undef PROC

    __syncthreads();

    // Reduce 30 bins * 32 lanes (over 8 warp-copies) -> 30 global atomics.
    // p-chunks are warp-aligned: within a chunk, b is warp-uniform, l == lane.
    for (int p = threadIdx.x; p < BINS * 32; p += THREADS) {
        int b = p >> 5;
        int l = p & 31;
        unsigned int s = 0;
        #pragma unroll
        for (int w = 0; w < WARPS; w++)
            s += sh[w * (NBIN_PAD * 32) + (b << 5) + l];
        #pragma unroll
        for (int off = 16; off; off >>= 1)
            s += __shfl_xor_sync(0xffffffffu, s, off);
        if (l == 0 && s) atomicAdd(&g_hist[which * NBIN_PAD + b], s);
    }
}

__global__ void mi_kernel(float* __restrict__ out) {
    if (threadIdx.x != 0) return;
    double hx[BINS], hy[BINS];
    double Sx = 0.0, Sy = 0.0;
    for (int b = 0; b < BINS; b++) {
        hx[b] = (double)g_hist[b];
        hy[b] = (double)g_hist[NBIN_PAD + b];
        Sx += hx[b];
        Sy += hy[b];
    }
    double Sj = Sx + Sy;
    double t_sum = 0.0, lx_sum = 0.0;
    for (int b = 0; b < BINS; b++) {
        double jp = (hx[b] + hy[b]) / Sj;
        double py = hy[b] / Sy;
        double px = hx[b] / Sx;
        t_sum  += jp * (log(jp) - log(py));
        lx_sum += log(px);
    }
    double mi = (double)BINS * t_sum - lx_sum;
    out[0] = (float)(-mi);
}

extern "C" void kernel_launch(void* const* d_in, const int* in_sizes, int n_in,
                              void* d_out, int out_size) {
    const float* x = (const float*)d_in[0];
    const float* y = (const float*)d_in[1];
    int nx = in_sizes[0];
    int ny = in_sizes[1];

    zero_kernel<<<1, 64>>>();
    hist_kernel<<<2 * BPA, THREADS>>>(x, y, nx, ny);
    mi_kernel<<<1, 32>>>((float*)d_out);
}

// round 2
// speedup vs baseline: 1.0674x; 1.0674x over previous
#include <cuda_runtime.h>

// MI loss over two 2^25 fp32 arrays.
// joint_hist == hist_x + hist_y  -> only two 30-bin histograms needed.
// Hot loop: per-lane-private smem histograms (no atomics, bank == lane so
// conflict-free). 7 blocks/SM (228KB smem budget) for latency hiding.
// Each block writes race-free partial sums; mi_kernel reduces + epilogue.

#define BINS 30
#define NBIN_PAD 32          // 30 bins + overflow slot (bin 30, never flushed)
#define THREADS 256
#define WARPS (THREADS / 32)
#define BPA 518              // blocks per array: 2*518 = 1036 = 7 per SM
#define NROWS 64             // 2 arrays * 32 padded bins

__device__ unsigned int g_part[NROWS * BPA];   // [row][block], race-free writes

__global__ void __launch_bounds__(THREADS) hist_kernel(
    const float* __restrict__ x, const float* __restrict__ y,
    int nx, int ny)
{
    // 8 warps * 32 bins * 32 lanes * 4B = 32 KB
    __shared__ unsigned int sh[WARPS * NBIN_PAD * 32];

    #pragma unroll
    for (int i = threadIdx.x; i < WARPS * NBIN_PAD * 32; i += THREADS) sh[i] = 0u;
    __syncthreads();

    const int which = (blockIdx.x >= BPA) ? 1 : 0;
    const float* __restrict__ src = which ? y : x;
    const int n = which ? ny : nx;
    const int bid = which ? ((int)blockIdx.x - BPA) : (int)blockIdx.x;

    const int warp = threadIdx.x >> 5;
    const int lane = threadIdx.x & 31;
    // lane-private column: addr = warp*4096B + bin*128B + lane*4B
    // bank(addr) == lane for every bin -> conflict-free RMW.
    unsigned int* __restrict__ h = sh + warp * (NBIN_PAD * 32) + lane;

    const float4* __restrict__ v4 = (const float4*)src;
    const int n4 = n >> 2;
    const int stride = BPA * THREADS;

#define PROC(val) {                                          \
        float t = fmaf((val), 3.75f, 15.0f);                 \
        int b = (int)floorf(t);                              \
        b = min(b, 29);                                      \
        bool ok = (t >= 0.0f) && (t <= 30.0f);               \
        if (!ok) b = 30;                                     \
        h[b << 5] += 1u; }

    #pragma unroll 4
    for (int i = bid * THREADS + threadIdx.x; i < n4; i += stride) {
        float4 v = v4[i];
        PROC(v.x)
        PROC(v.y)
        PROC(v.z)
        PROC(v.w)
    }

    // scalar tail (empty for N % 4 == 0)
    if (bid == 0) {
        for (int i = (n4 << 2) + threadIdx.x; i < n; i += THREADS) {
            float val = src[i];
            PROC(val)
        }
    }
#undef PROC

    __syncthreads();

    // Reduce 30 bins x 32 lanes over 8 warp-copies -> per-block partials.
    // Chunks are warp-aligned: within a chunk, bin is warp-uniform, l == lane.
    for (int p = threadIdx.x; p < BINS * 32; p += THREADS) {
        int b = p >> 5;
        int l = p & 31;
        unsigned int s = 0;
        #pragma unroll
        for (int w = 0; w < WARPS; w++)
            s += sh[w * (NBIN_PAD * 32) + (b << 5) + l];
        #pragma unroll
        for (int off = 16; off; off >>= 1)
            s += __shfl_xor_sync(0xffffffffu, s, off);
        if (l == 0)
            g_part[(which * NBIN_PAD + b) * BPA + bid] = s;   // race-free
    }
}

__global__ void __launch_bounds__(256) mi_kernel(float* __restrict__ out) {
    __shared__ unsigned long long tot[NROWS];
    const int warp = threadIdx.x >> 5;
    const int lane = threadIdx.x & 31;

    // 60 live rows, 8 warps; each warp reduces whole rows (coalesced).
    for (int r = warp; r < 2 * BINS; r += 8) {
        int which = r / BINS, b = r % BINS;
        int row = which * NBIN_PAD + b;
        unsigned long long s = 0;
        for (int j = lane; j < BPA; j += 32)
            s += (unsigned long long)g_part[row * BPA + j];
        #pragma unroll
        for (int off = 16; off; off >>= 1)
            s += __shfl_xor_sync(0xffffffffu, s, off);
        if (lane == 0) tot[row] = s;
    }
    __syncthreads();

    if (threadIdx.x == 0) {
        double hx[BINS], hy[BINS];
        double Sx = 0.0, Sy = 0.0;
        for (int b = 0; b < BINS; b++) {
            hx[b] = (double)tot[b];
            hy[b] = (double)tot[NBIN_PAD + b];
            Sx += hx[b];
            Sy += hy[b];
        }
        double Sj = Sx + Sy;
        double t_sum = 0.0, lx_sum = 0.0;
        for (int b = 0; b < BINS; b++) {
            double jp = (hx[b] + hy[b]) / Sj;
            double py = hy[b] / Sy;
            double px = hx[b] / Sx;
            t_sum  += jp * (log(jp) - log(py));
            lx_sum += log(px);
        }
        double mi = (double)BINS * t_sum - lx_sum;
        out[0] = (float)(-mi);
    }
}

extern "C" void kernel_launch(void* const* d_in, const int* in_sizes, int n_in,
                              void* d_out, int out_size) {
    const float* x = (const float*)d_in[0];
    const float* y = (const float*)d_in[1];
    int nx = in_sizes[0];
    int ny = in_sizes[1];

    hist_kernel<<<2 * BPA, THREADS>>>(x, y, nx, ny);
    mi_kernel<<<1, 256>>>((float*)d_out);
}

// round 3
// speedup vs baseline: 2.7123x; 2.5410x over previous
#include <cuda_runtime.h>

// MI loss over two 2^25 fp32 arrays.
// joint_hist == hist_x + hist_y  -> only two 30-bin histograms needed.
// Hot loop: per-lane-private smem histograms (no atomics, bank == lane so
// conflict-free), 7 blocks/SM. Race-free per-block partials; mi_kernel
// reduces them and computes the MI scalar with PER-LANE parallel fp64 logs
// (the R2 version did 90 dependent fp64 logs on ONE thread -> 128us).

#define BINS 30
#define NBIN_PAD 32          // 30 bins + overflow slot (bin 30, never flushed)
#define THREADS 256
#define WARPS (THREADS / 32)
#define BPA 518              // blocks per array: 2*518 = 1036 = 7 per SM
#define NROWS 64             // 2 arrays * 32 padded bins

__device__ unsigned int g_part[NROWS * BPA];   // [row][block], race-free writes

__global__ void __launch_bounds__(THREADS) hist_kernel(
    const float* __restrict__ x, const float* __restrict__ y,
    int nx, int ny)
{
    // 8 warps * 32 bins * 32 lanes * 4B = 32 KB
    __shared__ unsigned int sh[WARPS * NBIN_PAD * 32];

    #pragma unroll
    for (int i = threadIdx.x; i < WARPS * NBIN_PAD * 32; i += THREADS) sh[i] = 0u;
    __syncthreads();

    const int which = (blockIdx.x >= BPA) ? 1 : 0;
    const float* __restrict__ src = which ? y : x;
    const int n = which ? ny : nx;
    const int bid = which ? ((int)blockIdx.x - BPA) : (int)blockIdx.x;

    const int warp = threadIdx.x >> 5;
    const int lane = threadIdx.x & 31;
    // lane-private column: addr = warp*4096B + bin*128B + lane*4B
    // bank(addr) == lane for every bin -> conflict-free RMW.
    unsigned int* __restrict__ h = sh + warp * (NBIN_PAD * 32) + lane;

    const float4* __restrict__ v4 = (const float4*)src;
    const int n4 = n >> 2;
    const int stride = BPA * THREADS;

#define PROC(val) {                                          \
        float t = fmaf((val), 3.75f, 15.0f);                 \
        int b = (int)floorf(t);                              \
        b = min(b, 29);                                      \
        bool ok = (t >= 0.0f) && (t <= 30.0f);               \
        if (!ok) b = 30;                                     \
        h[b << 5] += 1u; }

    #pragma unroll 4
    for (int i = bid * THREADS + threadIdx.x; i < n4; i += stride) {
        float4 v = __ldcs(&v4[i]);     // streaming: zero reuse, skip L2 alloc
        PROC(v.x)
        PROC(v.y)
        PROC(v.z)
        PROC(v.w)
    }

    // scalar tail (empty for N % 4 == 0)
    if (bid == 0) {
        for (int i = (n4 << 2) + threadIdx.x; i < n; i += THREADS) {
            float val = __ldcs(&src[i]);
            PROC(val)
        }
    }
#undef PROC

    __syncthreads();

    // Reduce 30 bins x 32 lanes over 8 warp-copies -> per-block partials.
    for (int p = threadIdx.x; p < BINS * 32; p += THREADS) {
        int b = p >> 5;
        int l = p & 31;
        unsigned int s = 0;
        #pragma unroll
        for (int w = 0; w < WARPS; w++)
            s += sh[w * (NBIN_PAD * 32) + (b << 5) + l];
        #pragma unroll
        for (int off = 16; off; off >>= 1)
            s += __shfl_xor_sync(0xffffffffu, s, off);
        if (l == 0)
            g_part[(which * NBIN_PAD + b) * BPA + bid] = s;   // race-free
    }
}

__global__ void __launch_bounds__(256) mi_kernel(float* __restrict__ out) {
    __shared__ unsigned int tot[NROWS];
    const int warp = threadIdx.x >> 5;
    const int lane = threadIdx.x & 31;

    // 60 live rows, 8 warps; each warp reduces whole rows (coalesced).
    for (int r = warp; r < 2 * BINS; r += 8) {
        int which = r / BINS, b = r % BINS;
        int row = which * NBIN_PAD + b;
        unsigned int s = 0;
        for (int j = lane; j < BPA; j += 32)
            s += g_part[row * BPA + j];
        #pragma unroll
        for (int off = 16; off; off >>= 1)
            s += __shfl_xor_sync(0xffffffffu, s, off);
        if (lane == 0) tot[row] = s;
    }
    __syncthreads();

    // Epilogue: warp 0, lane b owns bin b. All logs run in parallel across
    // lanes (serial chain depth = 1 log, not 90).
    if (warp == 0) {
        bool live = (lane < BINS);
        double hx = live ? (double)tot[lane] : 0.0;
        double hy = live ? (double)tot[NBIN_PAD + lane] : 0.0;

        double Sx = hx, Sy = hy;
        #pragma unroll
        for (int off = 16; off; off >>= 1) {
            Sx += __shfl_xor_sync(0xffffffffu, Sx, off);
            Sy += __shfl_xor_sync(0xffffffffu, Sy, off);
        }
        double Sj = Sx + Sy;

        double term = 0.0, lx = 0.0;
        if (live) {
            double jp = (hx + hy) / Sj;
            double py = hy / Sy;
            double px = hx / Sx;
            term = jp * (log(jp) - log(py));
            lx = log(px);
        }
        #pragma unroll
        for (int off = 16; off; off >>= 1) {
            term += __shfl_xor_sync(0xffffffffu, term, off);
            lx   += __shfl_xor_sync(0xffffffffu, lx, off);
        }
        if (lane == 0) {
            double mi = (double)BINS * term - lx;
            out[0] = (float)(-mi);
        }
    }
}

extern "C" void kernel_launch(void* const* d_in, const int* in_sizes, int n_in,
                              void* d_out, int out_size) {
    const float* x = (const float*)d_in[0];
    const float* y = (const float*)d_in[1];
    int nx = in_sizes[0];
    int ny = in_sizes[1];

    hist_kernel<<<2 * BPA, THREADS>>>(x, y, nx, ny);
    mi_kernel<<<1, 256>>>((float*)d_out);
}

// round 5
// speedup vs baseline: 2.7880x; 1.0279x over previous
#include <cuda_runtime.h>

// MI loss over two 2^25 fp32 arrays.
// joint_hist == hist_x + hist_y -> only two 30-bin histograms needed.
// Hot loop: per-lane-private smem histograms (bank==lane, conflict-free,
// no atomics), 7 blocks/SM. Bin math is the R3-exact (passing) formula:
// floor(fma(v,3.75,15)) clamped, out-of-range -> trash slot 30.
// Race-free per-block partials; mi_kernel (32 warps, 1 warp/row) reduces
// and computes the scalar with per-lane parallel fp64 logs.

#define BINS 30
#define NBIN_PAD 32          // 30 bins + trash slots (never flushed)
#define THREADS 256
#define WARPS (THREADS / 32)
#define BPA 518              // blocks per array: 2*518 = 1036 = 7 per SM
#define NROWS 64             // 2 arrays * 32 padded bins

__device__ unsigned int g_part[NROWS * BPA];   // [row][block], race-free

__global__ void __launch_bounds__(THREADS, 7) hist_kernel(
    const float* __restrict__ x, const float* __restrict__ y,
    int nx, int ny)
{
    // 8 warps * 32 slots * 32 lanes * 4B = 32 KB
    __shared__ unsigned int sh[WARPS * NBIN_PAD * 32];

    for (int i = threadIdx.x; i < WARPS * NBIN_PAD * 32; i += THREADS) sh[i] = 0u;
    __syncthreads();

    const int which = (blockIdx.x >= BPA) ? 1 : 0;
    const float* __restrict__ src = which ? y : x;
    const int n = which ? ny : nx;
    const int bid = which ? ((int)blockIdx.x - BPA) : (int)blockIdx.x;

    const int warp = threadIdx.x >> 5;
    const int lane = threadIdx.x & 31;
    // lane-private column: addr = warp*4096B + slot*128B + lane*4B
    // bank(addr) == lane for every slot -> conflict-free RMW.
    unsigned int* __restrict__ h = sh + warp * (NBIN_PAD * 32) + lane;

    const float4* __restrict__ v4 = (const float4*)src;
    const int n4 = n >> 2;
    const int stride = BPA * THREADS;

    // R3-exact binning (known rel_err 7.28e-7):
    // t = fma(v, 3.75, 15); b = min(floor(t), 29); invalid -> slot 30.
    // __float2int_rd(t) == (int)floorf(t) for all t here (single F2I.RD).
#define PROC(val) {                                          \
        float t = fmaf((val), 3.75f, 15.0f);                 \
        int b = __float2int_rd(t);                           \
        b = min(b, 29);                                      \
        bool ok = (t >= 0.0f) && (t <= 30.0f);               \
        if (!ok) b = 30;                                     \
        h[b << 5] += 1u; }

    #pragma unroll 8
    for (int i = bid * THREADS + threadIdx.x; i < n4; i += stride) {
        float4 v = v4[i];
        PROC(v.x)
        PROC(v.y)
        PROC(v.z)
        PROC(v.w)
    }

    // scalar tail (empty when n % 4 == 0)
    if (bid == 0) {
        for (int i = (n4 << 2) + threadIdx.x; i < n; i += THREADS) {
            float val = src[i];
            PROC(val)
        }
    }
#undef PROC

    __syncthreads();

    // Reduce 30 bins x 32 lanes over 8 warp-copies -> per-block partials.
    for (int p = threadIdx.x; p < BINS * 32; p += THREADS) {
        int b = p >> 5;
        int l = p & 31;
        unsigned int s = 0;
        #pragma unroll
        for (int w = 0; w < WARPS; w++)
            s += sh[w * (NBIN_PAD * 32) + (b << 5) + l];
        #pragma unroll
        for (int off = 16; off; off >>= 1)
            s += __shfl_xor_sync(0xffffffffu, s, off);
        if (l == 0)
            g_part[(which * NBIN_PAD + b) * BPA + bid] = s;   // race-free
    }
}

__global__ void __launch_bounds__(1024) mi_kernel(float* __restrict__ out) {
    __shared__ unsigned int tot[NROWS];
    const int warp = threadIdx.x >> 5;
    const int lane = threadIdx.x & 31;

    // 60 live rows over 32 warps: one warp per row.
    // Each warp: 17 independent coalesced 128B loads -> high MLP.
    for (int r = warp; r < 2 * BINS; r += 32) {
        int which = r / BINS, b = r % BINS;
        int row = which * NBIN_PAD + b;
        unsigned int s = 0;
        #pragma unroll 4
        for (int j = lane; j < BPA; j += 32)
            s += g_part[row * BPA + j];
        #pragma unroll
        for (int off = 16; off; off >>= 1)
            s += __shfl_xor_sync(0xffffffffu, s, off);
        if (lane == 0) tot[row] = s;
    }
    __syncthreads();

    // Epilogue: warp 0, lane b owns bin b; fp64 logs run in parallel.
    if (warp == 0) {
        bool live = (lane < BINS);
        double hx = live ? (double)tot[lane] : 0.0;
        double hy = live ? (double)tot[NBIN_PAD + lane] : 0.0;

        double Sx = hx, Sy = hy;
        #pragma unroll
        for (int off = 16; off; off >>= 1) {
            Sx += __shfl_xor_sync(0xffffffffu, Sx, off);
            Sy += __shfl_xor_sync(0xffffffffu, Sy, off);
        }
        double Sj = Sx + Sy;

        double term = 0.0, lx = 0.0;
        if (live) {
            double jp = (hx + hy) / Sj;
            double py = hy / Sy;
            double px = hx / Sx;
            term = jp * (log(jp) - log(py));
            lx = log(px);
        }
        #pragma unroll
        for (int off = 16; off; off >>= 1) {
            term += __shfl_xor_sync(0xffffffffu, term, off);
            lx   += __shfl_xor_sync(0xffffffffu, lx, off);
        }
        if (lane == 0) {
            double mi = (double)BINS * term - lx;
            out[0] = (float)(-mi);
        }
    }
}

extern "C" void kernel_launch(void* const* d_in, const int* in_sizes, int n_in,
                              void* d_out, int out_size) {
    const float* x = (const float*)d_in[0];
    const float* y = (const float*)d_in[1];
    int nx = in_sizes[0];
    int ny = in_sizes[1];

    hist_kernel<<<2 * BPA, THREADS>>>(x, y, nx, ny);
    mi_kernel<<<1, 1024>>>((float*)d_out);
}